// round 2
// baseline (speedup 1.0000x reference)
#include <cuda_runtime.h>

#define Bv 8
#define Tv 1000
#define Dv 1024

// Scratch (__device__ globals per allocation rules)
__device__ float g_part[50 * 8 * 1024];   // per-chunk partial t-sums of x
__device__ float g_xsum[8 * 1024];        // sum_t x[b,t,:]
__device__ float g_vsum[8 * 64];          // sum_t v[b,t,:]
__device__ float g_wosum[64 * 1024];      // sum_h Wo[h*64+d, n]
__device__ float g_row[8 * 1024];         // per-batch output row

// ---------------------------------------------------------------------------
// 1) Partial sums over t: 50 chunks of 20 timesteps each, per batch.
//    grid (50, 8), 256 threads, float4 per thread (covers all 1024 cols).
// ---------------------------------------------------------------------------
__global__ void __launch_bounds__(256)
xsum_part_kernel(const float* __restrict__ x)
{
    const int chunk = blockIdx.x;       // 0..49
    const int b     = blockIdx.y;       // 0..7
    const int j4    = threadIdx.x << 2; // 0..1020

    const float4* xp = (const float4*)(x + ((size_t)b * Tv + chunk * 20) * Dv + j4);
    float4 acc = make_float4(0.f, 0.f, 0.f, 0.f);
    #pragma unroll
    for (int tt = 0; tt < 20; tt++) {
        float4 v = xp[(size_t)tt * (Dv / 4)];
        acc.x += v.x; acc.y += v.y; acc.z += v.z; acc.w += v.w;
    }
    *(float4*)(g_part + ((size_t)(chunk * 8 + b)) * Dv + j4) = acc;
}

// ---------------------------------------------------------------------------
// 2) Reduce the 50 partials -> g_xsum. grid (4, 8), 256 threads.
// ---------------------------------------------------------------------------
__global__ void __launch_bounds__(256)
xsum_reduce_kernel()
{
    const int j = blockIdx.x * 256 + threadIdx.x;  // 0..1023
    const int b = blockIdx.y;
    float s = 0.f;
    #pragma unroll
    for (int c = 0; c < 50; c++)
        s += g_part[((size_t)(c * 8 + b)) * Dv + j];
    g_xsum[b * Dv + j] = s;
}

// ---------------------------------------------------------------------------
// 3) Vsum[b,d] = g_xsum[b,:] @ Wv[:,d] + T*bv[d]. grid 8 (per b), 256 thr.
//    Threads: d = tid&63, 4 j-segments reduced via smem.
// ---------------------------------------------------------------------------
__global__ void __launch_bounds__(256)
vsum_kernel(const float* __restrict__ Wv, const float* __restrict__ bv)
{
    __shared__ float part[4][64];
    const int b   = blockIdx.x;
    const int d   = threadIdx.x & 63;
    const int seg = threadIdx.x >> 6;   // 0..3

    float s = 0.f;
    #pragma unroll 8
    for (int jj = 0; jj < 256; jj++) {
        int j = seg * 256 + jj;
        s += g_xsum[b * Dv + j] * Wv[(size_t)j * 64 + d];
    }
    part[seg][d] = s;
    __syncthreads();
    if (seg == 0)
        g_vsum[b * 64 + d] = part[0][d] + part[1][d] + part[2][d] + part[3][d]
                             + (float)Tv * bv[d];
}

// ---------------------------------------------------------------------------
// 4) WoSum[d,n] = sum_h Wo[h*64+d, n]. grid (4, 64), 256 threads.
// ---------------------------------------------------------------------------
__global__ void __launch_bounds__(256)
wosum_kernel(const float* __restrict__ Wo)
{
    const int n = blockIdx.x * 256 + threadIdx.x;
    const int d = blockIdx.y;
    float s = 0.f;
    #pragma unroll
    for (int h = 0; h < 16; h++)
        s += Wo[((size_t)(h * 64 + d)) * Dv + n];
    g_wosum[(size_t)d * Dv + n] = s;
}

// ---------------------------------------------------------------------------
// 5) row[b,n] = bo[n] + sum_d Vsum[b,d] * WoSum[d,n]. grid (4, 8), 256 thr.
// ---------------------------------------------------------------------------
__global__ void __launch_bounds__(256)
row_kernel(const float* __restrict__ bo)
{
    const int n = blockIdx.x * 256 + threadIdx.x;
    const int b = blockIdx.y;
    float s = bo[n];
    #pragma unroll
    for (int d = 0; d < 64; d++)
        s += g_vsum[b * 64 + d] * g_wosum[(size_t)d * Dv + n];
    g_row[b * Dv + n] = s;
}

// ---------------------------------------------------------------------------
// 6) Broadcast row to every timestep. grid 8000, 256 threads, float4.
//    out[b,t,:] = row[b,:]
// ---------------------------------------------------------------------------
__global__ void __launch_bounds__(256)
bcast_kernel(float* __restrict__ out)
{
    const size_t idx = (size_t)blockIdx.x * 256 + threadIdx.x;   // float4 idx
    const int b  = (int)(idx / ((size_t)Tv * 256));
    const int n4 = (int)(idx & 255);
    ((float4*)out)[idx] = ((const float4*)g_row)[b * 256 + n4];
}

// ---------------------------------------------------------------------------
extern "C" void kernel_launch(void* const* d_in, const int* in_sizes, int n_in,
                              void* d_out, int out_size)
{
    const float* x  = (const float*)d_in[0];
    const float* Wv = (const float*)d_in[5];
    const float* bv = (const float*)d_in[6];
    const float* Wo = (const float*)d_in[7];
    const float* bo = (const float*)d_in[8];
    float* out = (float*)d_out;

    xsum_part_kernel<<<dim3(50, 8), 256>>>(x);
    xsum_reduce_kernel<<<dim3(4, 8), 256>>>();
    vsum_kernel<<<8, 256>>>(Wv, bv);
    wosum_kernel<<<dim3(4, 64), 256>>>(Wo);
    row_kernel<<<dim3(4, 8), 256>>>(bo);
    bcast_kernel<<<(Bv * Tv * Dv) / (256 * 4), 256>>>(out);
}